// round 15
// baseline (speedup 1.0000x reference)
#include <cuda_runtime.h>
#include <cuda_fp16.h>
#include <cuda_fp8.h>
#include <math.h>
#include <stdint.h>

#define Bn 4096
#define HSLOT ((size_t)Bn * 512)
#define STAGE_BYTES 36864
#define SMEM_BYTES (3 * STAGE_BYTES)

// Gate permutation: physical col p (p<2048) <-> logical (gate g, unit j):
//   g = (p>>3)&3, j = ((p>>5)<<3) + (p&7)

// ---------------- device scratch ----------------
__device__ unsigned char g_Ah8[(size_t)17 * HSLOT];   // slot j+1: h_j (e4m3); slot 0 unused
__device__ __half g_Ah16f[HSLOT];                     // fp16 copy of h_15 for head
__device__ __half g_APRE[(size_t)65536 * 64];
__device__ unsigned char g_WTb8[(size_t)3072 * 512];  // [Uh(perm)|Wa|We] e4m3, n-major
__device__ __half g_WPRE[(size_t)2560 * 64];
__device__ unsigned char g_WT28[1024 * 512];          // [Wb | Wg] e4m3
__device__ __half g_WTh[256 * 512];                   // W1
__device__ __half g_ZX16[(size_t)16 * Bn * 2048];
__device__ __half g_TG16[(size_t)16 * Bn * 512];
__device__ unsigned char g_MEMA8[(size_t)15 * HSLOT]; // slot j: h_j @ Wa, e4m3
__device__ __half g_HWE16[(size_t)15 * HSLOT];        // slot j: h_j @ We
__device__ unsigned char g_Hc8[(size_t)Bn * 512];     // o*tanh(c), e4m3
__device__ __half g_HBh[(size_t)Bn * 512];
__device__ __half g_HGh[(size_t)Bn * 512];
__device__ float g_C[(size_t)Bn * 512];
__device__ float g_HD1[(size_t)Bn * 256];
__device__ float g_HD2[(size_t)Bn * 32];
__device__ float g_s[512];
__device__ float g_sA[512];
__device__ float g_sWe[512];

__device__ __forceinline__ float sigm(float x) { return 1.f / (1.f + expf(-x)); }
__device__ __forceinline__ float sigmf_(float x) { return __fdividef(1.f, 1.f + __expf(-x)); }
__device__ __forceinline__ float tanh_app(float x) {
    float y; asm("tanh.approx.f32 %0, %1;" : "=f"(y) : "f"(x)); return y;
}

__device__ __forceinline__ uint32_t smem_u32(const void* p) {
    uint32_t a;
    asm("{ .reg .u64 t; cvta.to.shared.u64 t, %1; cvt.u32.u64 %0, t; }" : "=r"(a) : "l"(p));
    return a;
}
__device__ __forceinline__ void ldm4(uint32_t* r, uint32_t a) {
    asm volatile("ldmatrix.sync.aligned.m8n8.x4.shared.b16 {%0,%1,%2,%3}, [%4];"
                 : "=r"(r[0]), "=r"(r[1]), "=r"(r[2]), "=r"(r[3]) : "r"(a));
}
__device__ __forceinline__ void mma16816(float* c, const uint32_t* a, uint32_t b0, uint32_t b1) {
    asm volatile("mma.sync.aligned.m16n8k16.row.col.f32.f16.f16.f32 "
                 "{%0,%1,%2,%3}, {%4,%5,%6,%7}, {%8,%9}, {%0,%1,%2,%3};"
                 : "+f"(c[0]), "+f"(c[1]), "+f"(c[2]), "+f"(c[3])
                 : "r"(a[0]), "r"(a[1]), "r"(a[2]), "r"(a[3]), "r"(b0), "r"(b1));
}
__device__ __forceinline__ void mma16832f8(float* c, const uint32_t* a, uint32_t b0, uint32_t b1) {
    asm volatile("mma.sync.aligned.m16n8k32.row.col.f32.e4m3.e4m3.f32 "
                 "{%0,%1,%2,%3}, {%4,%5,%6,%7}, {%8,%9}, {%0,%1,%2,%3};"
                 : "+f"(c[0]), "+f"(c[1]), "+f"(c[2]), "+f"(c[3])
                 : "r"(a[0]), "r"(a[1]), "r"(a[2]), "r"(a[3]), "r"(b0), "r"(b1));
}
__device__ __forceinline__ void cp16(uint32_t saddr, const void* gptr) {
    asm volatile("cp.async.cg.shared.global [%0], [%1], 16;"
                 :: "r"(saddr), "l"(__cvta_generic_to_global(gptr)) : "memory");
}
__device__ __forceinline__ void cp_commit() {
    asm volatile("cp.async.commit_group;" ::: "memory");
}
__device__ __forceinline__ __nv_fp8x2_storage_t f2_to_fp8x2(float x, float y) {
    return __nv_cvt_float2_to_fp8x2(make_float2(x, y), __NV_SATFINITE, __NV_E4M3);
}

// ---------------- prep kernels ----------------
__global__ void prep_weights(const float* __restrict__ Uh, const float* __restrict__ Wx,
                             const float* __restrict__ Wt, const float* __restrict__ Wa,
                             const float* __restrict__ WxT, const float* __restrict__ Wb,
                             const float* __restrict__ Wg, const float* __restrict__ We,
                             const float* __restrict__ W1) {
    int stride = gridDim.x * blockDim.x;
    int t0 = blockIdx.x * blockDim.x + threadIdx.x;
    for (int i = t0; i < 3072 * 512; i += stride) {
        int n = i >> 9, k = i & 511;
        float w;
        if (n < 2048) {
            int g = (n >> 3) & 3, j = ((n >> 5) << 3) + (n & 7);
            w = Uh[(size_t)k * 2048 + g * 512 + j];
        } else if (n < 2560) {
            w = Wa[(size_t)k * 512 + (n - 2048)];
        } else {
            w = We[(size_t)k * 512 + (n - 2560)];
        }
        g_WTb8[i] = __nv_cvt_float_to_fp8(w, __NV_SATFINITE, __NV_E4M3);
    }
    for (int i = t0; i < 2560 * 64; i += stride) {
        int n = i >> 6, k = i & 63;
        float w;
        if (n < 2048) {
            int g = (n >> 3) & 3, j = ((n >> 5) << 3) + (n & 7);
            if (k < 63) w = Wx[(size_t)k * 2048 + g * 512 + j];
            else        w = (g < 3) ? Wt[g * 512 + j] : 0.f;
        } else {
            w = (k < 63) ? WxT[(size_t)k * 512 + (n - 2048)] : 0.f;
        }
        g_WPRE[i] = __float2half(w);
    }
    for (int i = t0; i < 1024 * 512; i += stride) {
        int n = i >> 9, k = i & 511;
        float w = (n < 512) ? Wb[(size_t)k * 512 + n] : Wg[(size_t)k * 512 + (n - 512)];
        g_WT28[i] = __nv_cvt_float_to_fp8(w, __NV_SATFINITE, __NV_E4M3);
    }
    for (int i = t0; i < 256 * 512; i += stride) {
        int n = i >> 9, k = i & 511;
        g_WTh[i] = __float2half(W1[(size_t)k * 256 + n]);
    }
}

__global__ void prep_s(const float* __restrict__ init_proj) {
    int h = threadIdx.x;
    float s = 0.f;
    for (int f = 0; f < 64; ++f) s += init_proj[f * 512 + h];
    g_s[h] = s;
}

__global__ void prep_sA(const float* __restrict__ Wa, const float* __restrict__ We) {
    int h = threadIdx.x;
    float a = 0.f, e = 0.f;
    for (int k = 0; k < 512; ++k) {
        float sv = g_s[k];
        a = fmaf(sv, Wa[k * 512 + h], a);
        e = fmaf(sv, We[k * 512 + h], e);
    }
    g_sA[h] = a;
    g_sWe[h] = e;
}

__global__ void prep_A(const float* __restrict__ inp) {
    int stride = gridDim.x * blockDim.x;
    int t0 = blockIdx.x * blockDim.x + threadIdx.x;
    for (int i = t0; i < 65536 * 64; i += stride) {
        int r = i >> 6, k = i & 63;
        float v = (k < 63) ? inp[(size_t)r * 64 + 1 + k] : inp[(size_t)r * 64];
        g_APRE[i] = __float2half(v);
    }
}

// ---------------- fp8 e4m3 HMMA GEMM (MODE 1, 2); K in elements (==bytes) ----------------
// chunk = 128 k-elems (128B/row), kch = K/128; fragments byte-identical to fp16 path.
// MODE 1: N=3072 [Uh(perm)|Wa|We]: n<2048 -> FUSED gates -> C, Hc8;
//         2048..2559 -> MEMA8 slot; 2560..3071 -> HWE16 slot
// MODE 2: N=1024 [Wb|Wg]: c<512 -> HBh(+e0); else HGh
template <int MODE>
__global__ __launch_bounds__(256, 2)
void fp8_gemm(const unsigned char* __restrict__ A, int K,
              const unsigned char* __restrict__ Bh,
              const float* __restrict__ e0,
              unsigned char* __restrict__ hc8,
              unsigned char* __restrict__ mema, __half* __restrict__ hwe,
              __half* __restrict__ hb, __half* __restrict__ hg,
              const __half* __restrict__ zxp, const __half* __restrict__ tgp,
              float* __restrict__ Cp) {
    extern __shared__ char smem[];
    uint32_t sb = smem_u32(smem);
    const int tid = threadIdx.x;
    const int lane = tid & 31, wid = tid >> 5;
    const int wm = wid & 1, wn = wid >> 1;
    const int gid = lane >> 2, tq = lane & 3;
    const int m0 = blockIdx.y * 128, n0 = blockIdx.x * 128;

    const int kch = K >> 7;   // 128 k-elems per chunk

    float acc[4][4][4];
    #pragma unroll
    for (int a = 0; a < 4; ++a)
        #pragma unroll
        for (int b2 = 0; b2 < 4; ++b2)
            #pragma unroll
            for (int c = 0; c < 4; ++c) acc[a][b2][c] = 0.f;

    auto copy_chunk = [&](int ch, int s) {
        int kc = ch << 7;
        uint32_t base = sb + s * STAGE_BYTES;
        #pragma unroll
        for (int i = 0; i < 4; ++i) {
            int lin = tid + (i << 8);
            int r = lin >> 3;
            int c16 = (lin & 7) << 4;
            cp16(base + r * 144 + c16, A + (size_t)(m0 + r) * K + kc + c16);
            cp16(base + 18432 + r * 144 + c16, Bh + (size_t)(n0 + r) * K + kc + c16);
        }
    };

    copy_chunk(0, 0);
    cp_commit();
    if (kch > 1) { copy_chunk(1, 1); cp_commit(); }

    const int arow = wm * 64 + (lane & 15);
    const int acol = (lane >> 4) << 4;
    const int brow = wn * 32 + (lane & 7) + ((lane >> 4) << 3);
    const int bcol = ((lane >> 3) & 1) << 4;

    for (int ch = 0; ch < kch; ++ch) {
        if (ch + 1 < kch) {
            asm volatile("cp.async.wait_group 1;" ::: "memory");
        } else {
            asm volatile("cp.async.wait_group 0;" ::: "memory");
        }
        __syncthreads();

        int buf = ch % 3;
        uint32_t abase = sb + buf * STAGE_BYTES;
        uint32_t bbase = abase + 18432;
        #pragma unroll
        for (int k32 = 0; k32 < 4; ++k32) {
            int kb = k32 << 5;
            uint32_t bf[2][4];
            #pragma unroll
            for (int ni2 = 0; ni2 < 2; ++ni2)
                ldm4(bf[ni2], bbase + (brow + ni2 * 16) * 144 + kb + bcol);
            uint32_t af[4][4];
            #pragma unroll
            for (int mi = 0; mi < 4; ++mi)
                ldm4(af[mi], abase + (arow + mi * 16) * 144 + kb + acol);
            #pragma unroll
            for (int ni2 = 0; ni2 < 2; ++ni2)
                #pragma unroll
                for (int mi = 0; mi < 4; ++mi) {
                    mma16832f8(acc[mi][ni2 * 2],     af[mi], bf[ni2][0], bf[ni2][1]);
                    mma16832f8(acc[mi][ni2 * 2 + 1], af[mi], bf[ni2][2], bf[ni2][3]);
                }
        }
        if (ch + 2 < kch) {
            copy_chunk(ch + 2, (ch + 2) % 3);
            cp_commit();
        }
    }

    // ---- epilogues ----
    if (MODE == 1) {
        if (n0 < 2048) {
            int blk = (n0 + wn * 32) >> 5;
            int j = blk * 8 + (tq << 1);
            #pragma unroll
            for (int mi = 0; mi < 4; ++mi) {
                int mb = m0 + wm * 64 + mi * 16 + gid;
                #pragma unroll
                for (int hf = 0; hf < 2; ++hf) {
                    int r = mb + hf * 8;
                    int ko = hf * 2;
                    const __half* zxr = zxp + (size_t)r * 2048 + blk * 32 + (tq << 1);
                    float2 xi = __half22float2(*(const __half2*)(zxr));
                    float2 xf = __half22float2(*(const __half2*)(zxr + 8));
                    float2 xo = __half22float2(*(const __half2*)(zxr + 16));
                    float2 xc = __half22float2(*(const __half2*)(zxr + 24));
                    float2 tg2 = __half22float2(*(const __half2*)(tgp + (size_t)r * 512 + j));
                    float2 cold = *(float2*)(Cp + (size_t)r * 512 + j);
                    float ch0 = tanh_app(acc[mi][3][ko] + xc.x);
                    float ch1 = tanh_app(acc[mi][3][ko + 1] + xc.y);
                    float c0 = fmaf(sigmf_(acc[mi][1][ko] + xf.x), cold.x,
                                    (sigmf_(acc[mi][0][ko] + xi.x) + tg2.x) * ch0);
                    float c1 = fmaf(sigmf_(acc[mi][1][ko + 1] + xf.y), cold.y,
                                    (sigmf_(acc[mi][0][ko + 1] + xi.y) + tg2.y) * ch1);
                    *(float2*)(Cp + (size_t)r * 512 + j) = make_float2(c0, c1);
                    float h0 = sigmf_(acc[mi][2][ko] + xo.x) * tanh_app(c0);
                    float h1 = sigmf_(acc[mi][2][ko + 1] + xo.y) * tanh_app(c1);
                    *(__nv_fp8x2_storage_t*)(hc8 + (size_t)r * 512 + j) = f2_to_fp8x2(h0, h1);
                }
            }
        } else if (n0 < 2560) {
            #pragma unroll
            for (int mi = 0; mi < 4; ++mi)
                #pragma unroll
                for (int ni = 0; ni < 4; ++ni) {
                    float* cc = acc[mi][ni];
                    int m = m0 + wm * 64 + mi * 16 + gid;
                    int c = n0 + wn * 32 + ni * 8 + (tq << 1) - 2048;
                    *(__nv_fp8x2_storage_t*)(mema + (size_t)m * 512 + c) = f2_to_fp8x2(cc[0], cc[1]);
                    *(__nv_fp8x2_storage_t*)(mema + (size_t)(m + 8) * 512 + c) = f2_to_fp8x2(cc[2], cc[3]);
                }
        } else {
            #pragma unroll
            for (int mi = 0; mi < 4; ++mi)
                #pragma unroll
                for (int ni = 0; ni < 4; ++ni) {
                    float* cc = acc[mi][ni];
                    int m = m0 + wm * 64 + mi * 16 + gid;
                    int c = n0 + wn * 32 + ni * 8 + (tq << 1) - 2560;
                    *(__half2*)(hwe + (size_t)m * 512 + c) = __floats2half2_rn(cc[0], cc[1]);
                    *(__half2*)(hwe + (size_t)(m + 8) * 512 + c) = __floats2half2_rn(cc[2], cc[3]);
                }
        }
    } else {  // MODE 2
        #pragma unroll
        for (int mi = 0; mi < 4; ++mi)
            #pragma unroll
            for (int ni = 0; ni < 4; ++ni) {
                float* cc = acc[mi][ni];
                int m = m0 + wm * 64 + mi * 16 + gid;
                int c = n0 + wn * 32 + ni * 8 + (tq << 1);
                if (c < 512) {
                    float b0 = e0[c], b1 = e0[c + 1];
                    *(__half2*)(hb + (size_t)m * 512 + c) = __floats2half2_rn(cc[0] + b0, cc[1] + b1);
                    *(__half2*)(hb + (size_t)(m + 8) * 512 + c) = __floats2half2_rn(cc[2] + b0, cc[3] + b1);
                } else {
                    int cj = c - 512;
                    *(__half2*)(hg + (size_t)m * 512 + cj) = __floats2half2_rn(cc[0], cc[1]);
                    *(__half2*)(hg + (size_t)(m + 8) * 512 + cj) = __floats2half2_rn(cc[2], cc[3]);
                }
            }
    }
}

// ---------------- fp16 HMMA GEMM (MODE 4 head, MODE 5 pre) ----------------
template <int MODE>
__global__ __launch_bounds__(256, 2)
void mma_gemm(const __half* __restrict__ A, int lda, int K,
              const __half* __restrict__ Bh,
              const float* __restrict__ e0, float* __restrict__ o0,
              const float* __restrict__ inp, const float* __restrict__ WtT,
              const float* __restrict__ bT) {
    extern __shared__ char smem[];
    uint32_t sb = smem_u32(smem);
    const int tid = threadIdx.x;
    const int lane = tid & 31, wid = tid >> 5;
    const int wm = wid & 1, wn = wid >> 1;
    const int gid = lane >> 2, tq = lane & 3;
    const int m0 = blockIdx.y * 128, n0 = blockIdx.x * 128;
    const int kch = K >> 6;

    float acc[4][4][4];
    #pragma unroll
    for (int a = 0; a < 4; ++a)
        #pragma unroll
        for (int b2 = 0; b2 < 4; ++b2)
            #pragma unroll
            for (int c = 0; c < 4; ++c) acc[a][b2][c] = 0.f;

    auto copy_chunk = [&](int ch, int s) {
        int kc = ch << 6;
        uint32_t base = sb + s * STAGE_BYTES;
        #pragma unroll
        for (int i = 0; i < 4; ++i) {
            int lin = tid + (i << 8);
            int r = lin >> 3;
            int c16 = (lin & 7) << 4;
            cp16(base + r * 144 + c16,
                 (const char*)(A + (size_t)(m0 + r) * lda + kc) + c16);
            cp16(base + 18432 + r * 144 + c16,
                 (const char*)(Bh + (size_t)(n0 + r) * K + kc) + c16);
        }
    };

    copy_chunk(0, 0);
    cp_commit();
    if (kch > 1) { copy_chunk(1, 1); cp_commit(); }

    const int arow = wm * 64 + (lane & 15);
    const int acol = (lane >> 4) << 4;
    const int brow = wn * 32 + (lane & 7) + ((lane >> 4) << 3);
    const int bcol = ((lane >> 3) & 1) << 4;

    for (int ch = 0; ch < kch; ++ch) {
        if (ch + 1 < kch) {
            asm volatile("cp.async.wait_group 1;" ::: "memory");
        } else {
            asm volatile("cp.async.wait_group 0;" ::: "memory");
        }
        __syncthreads();

        int buf = ch % 3;
        uint32_t abase = sb + buf * STAGE_BYTES;
        uint32_t bbase = abase + 18432;
        #pragma unroll
        for (int k16 = 0; k16 < 4; ++k16) {
            int kb = k16 << 5;
            uint32_t bf[2][4];
            #pragma unroll
            for (int ni2 = 0; ni2 < 2; ++ni2)
                ldm4(bf[ni2], bbase + (brow + ni2 * 16) * 144 + kb + bcol);
            uint32_t af[4][4];
            #pragma unroll
            for (int mi = 0; mi < 4; ++mi)
                ldm4(af[mi], abase + (arow + mi * 16) * 144 + kb + acol);
            #pragma unroll
            for (int ni2 = 0; ni2 < 2; ++ni2)
                #pragma unroll
                for (int mi = 0; mi < 4; ++mi) {
                    mma16816(acc[mi][ni2 * 2],     af[mi], bf[ni2][0], bf[ni2][1]);
                    mma16816(acc[mi][ni2 * 2 + 1], af[mi], bf[ni2][2], bf[ni2][3]);
                }
        }
        if (ch + 2 < kch) {
            copy_chunk(ch + 2, (ch + 2) % 3);
            cp_commit();
        }
    }

    auto epi = [&](int m, int c, float x, float y) {
        if (MODE == 4) {
            *(float2*)(o0 + (size_t)m * 256 + c) =
                make_float2(fmaxf(x + e0[c], 0.f), fmaxf(y + e0[c + 1], 0.f));
        } else {  // MODE 5
            int b_ = m >> 4, t_ = m & 15;
            size_t zr = (size_t)t_ * Bn + b_;
            if (c < 2048) {
                int g = (c >> 3) & 3;
                int j0 = ((c >> 5) << 3) + (c & 7);
                *(__half2*)(g_ZX16 + zr * 2048 + c) =
                    __floats2half2_rn(x + e0[g * 512 + j0], y + e0[g * 512 + j0 + 1]);
            } else {
                int j = c - 2048;
                float tv = inp[(size_t)m * 64];
                float t0v = sigm(x + sigm(tv * WtT[j]) + bT[j]);
                float t1v = sigm(y + sigm(tv * WtT[j + 1]) + bT[j + 1]);
                *(__half2*)(g_TG16 + zr * 512 + j) = __floats2half2_rn(t0v, t1v);
            }
        }
    };

    #pragma unroll
    for (int mi = 0; mi < 4; ++mi) {
        #pragma unroll
        for (int ni = 0; ni < 4; ++ni) {
            float* cc = acc[mi][ni];
            int m = m0 + wm * 64 + mi * 16 + gid;
            int c = n0 + wn * 32 + ni * 8 + (tq << 1);
            epi(m, c, cc[0], cc[1]);
            epi(m + 8, c, cc[2], cc[3]);
        }
    }
}

// ---------------- t=0 gates ----------------
__global__ void gates0_k(const __half* __restrict__ ZX, const __half* __restrict__ TG,
                         float* __restrict__ C, unsigned char* __restrict__ Hc8) {
    int idx = blockIdx.x * blockDim.x + threadIdx.x;
    int b = idx >> 9, j = idx & 511;
    int blk = j >> 3, jr = j & 7;
    const __half* zx = ZX + (size_t)b * 2048 + blk * 32 + jr;
    float zi = __half2float(zx[0]);
    float zo = __half2float(zx[16]);
    float zc = __half2float(zx[24]);
    float tg = __half2float(TG[idx]);
    float ch = tanh_app(zc);
    float c = (sigmf_(zi) + tg) * ch;
    C[idx] = c;
    Hc8[idx] = __nv_cvt_float_to_fp8(sigmf_(zo) * tanh_app(c), __NV_SATFINITE, __NV_E4M3);
}

// ---------------- attention + h_new epilogue (fp8 MEMA, fp16 HWE) ----------------
__global__ void __launch_bounds__(256) attn_k(const __half* __restrict__ HB,
                                              const __half* __restrict__ HG,
                                              const float* __restrict__ va,
                                              const float* __restrict__ bhv,
                                              unsigned char* __restrict__ Ah8Next,
                                              __half* __restrict__ Ah16, int t) {
    int b = blockIdx.x, tid = threadIdx.x;
    __shared__ float sred[15][8];
    __shared__ float se[15];
    float2 hb = __half22float2(((const __half2*)(HB + (size_t)b * 512))[tid]);
    float2 va2 = *(const float2*)(va + 2 * tid);
    float2 sA2 = *(const float2*)(g_sA + 2 * tid);
    float2 sW2 = *(const float2*)(g_sWe + 2 * tid);
    int lane = tid & 31, wp = tid >> 5;

    #pragma unroll
    for (int d = 0; d < 15; ++d) {
        int j = t - 15 + d;
        float m0, m1;
        if (j < 0) {
            m0 = sA2.x; m1 = sA2.y;
        } else {
            __nv_fp8x2_storage_t raw =
                ((const __nv_fp8x2_storage_t*)(g_MEMA8 + (size_t)j * HSLOT + (size_t)b * 512))[tid];
            __half2_raw hr = __nv_cvt_fp8x2_to_halfraw2(raw, __NV_E4M3);
            float2 f = __half22float2(*(__half2*)&hr);
            m0 = f.x; m1 = f.y;
        }
        float s = va2.x * tanh_app(m0 + hb.x) + va2.y * tanh_app(m1 + hb.y);
        #pragma unroll
        for (int off = 16; off; off >>= 1) s += __shfl_xor_sync(0xffffffffu, s, off);
        if (lane == 0) sred[d][wp] = s;
    }
    __syncthreads();
    if (tid < 15) {
        float e = 0.f;
        #pragma unroll
        for (int w2 = 0; w2 < 8; ++w2) e += sred[tid][w2];
        se[tid] = e;
    }
    __syncthreads();

    float mx = -1e30f;
    #pragma unroll
    for (int d = 0; d < 15; ++d) mx = fmaxf(mx, se[d]);
    float al[15], sum = 0.f;
    #pragma unroll
    for (int d = 0; d < 15; ++d) { al[d] = __expf(se[d] - mx); sum += al[d]; }
    float inv = __fdividef(1.f, sum);
    float c0 = 0.f, c1 = 0.f;
    #pragma unroll
    for (int d = 0; d < 15; ++d) {
        int j = t - 15 + d;
        float a = al[d] * inv;
        float m0, m1;
        if (j < 0) {
            m0 = sW2.x; m1 = sW2.y;
        } else {
            float2 f = __half22float2(
                ((const __half2*)(g_HWE16 + (size_t)j * HSLOT + (size_t)b * 512))[tid]);
            m0 = f.x; m1 = f.y;
        }
        c0 = fmaf(a, m0, c0);
        c1 = fmaf(a, m1, c1);
    }
    float2 hg = __half22float2(((const __half2*)(HG + (size_t)b * 512))[tid]);
    float2 bh2 = *(const float2*)(bhv + 2 * tid);
    float h0 = tanh_app(c0 + hg.x + bh2.x);
    float h1 = tanh_app(c1 + hg.y + bh2.y);
    ((__nv_fp8x2_storage_t*)(Ah8Next + (size_t)b * 512))[tid] = f2_to_fp8x2(h0, h1);
    if (t == 15)
        ((__half2*)(Ah16 + (size_t)b * 512))[tid] = __floats2half2_rn(h0, h1);
}

// ---------------- head layers 2,3 ----------------
__global__ void head2_k(const float* __restrict__ HD1, const float* __restrict__ W2,
                        const float* __restrict__ b2, float* __restrict__ HD2) {
    int warp = (blockIdx.x * blockDim.x + threadIdx.x) >> 5;
    int lane = threadIdx.x & 31;
    if (warp >= Bn) return;
    const float* h = HD1 + (size_t)warp * 256;
    float acc = 0.f;
    for (int k = 0; k < 256; ++k) acc = fmaf(h[k], W2[k * 32 + lane], acc);
    HD2[(size_t)warp * 32 + lane] = fmaxf(acc + b2[lane], 0.f);
}

__global__ void head3_k(const float* __restrict__ HD2, const float* __restrict__ W3,
                        const float* __restrict__ b3, float* __restrict__ out) {
    int b = blockIdx.x * blockDim.x + threadIdx.x;
    if (b >= Bn) return;
    float a0 = b3[0], a1 = b3[1];
    const float* h = HD2 + (size_t)b * 32;
    #pragma unroll
    for (int k = 0; k < 32; ++k) {
        float hv = h[k];
        a0 = fmaf(hv, W3[k * 2 + 0], a0);
        a1 = fmaf(hv, W3[k * 2 + 1], a1);
    }
    float m = fmaxf(a0, a1);
    float e0v = expf(a0 - m), e1v = expf(a1 - m);
    float inv = 1.f / (e0v + e1v);
    out[(size_t)b * 2 + 0] = e0v * inv;
    out[(size_t)b * 2 + 1] = e1v * inv;
}

// ---------------- launcher ----------------
extern "C" void kernel_launch(void* const* d_in, const int* in_sizes, int n_in,
                              void* d_out, int out_size) {
    const float* inputs    = (const float*)d_in[0];
    const float* init_proj = (const float*)d_in[1];
    const float* Wx  = (const float*)d_in[3];
    const float* Uh  = (const float*)d_in[4];
    const float* Wt  = (const float*)d_in[5];
    const float* b   = (const float*)d_in[6];
    const float* WxT = (const float*)d_in[7];
    const float* WtT = (const float*)d_in[8];
    const float* bT  = (const float*)d_in[9];
    const float* Wa  = (const float*)d_in[10];
    const float* Wb  = (const float*)d_in[11];
    const float* va  = (const float*)d_in[12];
    const float* ba  = (const float*)d_in[13];
    const float* We  = (const float*)d_in[14];
    const float* Wg  = (const float*)d_in[15];
    const float* bh  = (const float*)d_in[16];
    const float* W1  = (const float*)d_in[17];
    const float* b1  = (const float*)d_in[18];
    const float* W2  = (const float*)d_in[19];
    const float* b2  = (const float*)d_in[20];
    const float* W3  = (const float*)d_in[21];
    const float* b3  = (const float*)d_in[22];
    float* out = (float*)d_out;

    cudaFuncSetAttribute(fp8_gemm<1>, cudaFuncAttributeMaxDynamicSharedMemorySize, SMEM_BYTES);
    cudaFuncSetAttribute(fp8_gemm<2>, cudaFuncAttributeMaxDynamicSharedMemorySize, SMEM_BYTES);
    cudaFuncSetAttribute(mma_gemm<4>, cudaFuncAttributeMaxDynamicSharedMemorySize, SMEM_BYTES);
    cudaFuncSetAttribute(mma_gemm<5>, cudaFuncAttributeMaxDynamicSharedMemorySize, SMEM_BYTES);

    unsigned char *Ah8, *WTb8, *WT28, *MEMA8, *Hc8;
    __half *Ah16f, *APRE, *WPRE, *WTh, *HWE16, *ZX16, *TG16, *HBh, *HGh;
    float *C, *HD1, *HD2;
    cudaGetSymbolAddress((void**)&Ah8, g_Ah8);
    cudaGetSymbolAddress((void**)&Ah16f, g_Ah16f);
    cudaGetSymbolAddress((void**)&APRE, g_APRE);
    cudaGetSymbolAddress((void**)&WTb8, g_WTb8);
    cudaGetSymbolAddress((void**)&WPRE, g_WPRE);
    cudaGetSymbolAddress((void**)&WT28, g_WT28);
    cudaGetSymbolAddress((void**)&WTh, g_WTh);
    cudaGetSymbolAddress((void**)&MEMA8, g_MEMA8);
    cudaGetSymbolAddress((void**)&HWE16, g_HWE16);
    cudaGetSymbolAddress((void**)&ZX16, g_ZX16);
    cudaGetSymbolAddress((void**)&TG16, g_TG16);
    cudaGetSymbolAddress((void**)&Hc8, g_Hc8);
    cudaGetSymbolAddress((void**)&HBh, g_HBh);
    cudaGetSymbolAddress((void**)&HGh, g_HGh);
    cudaGetSymbolAddress((void**)&C, g_C);
    cudaGetSymbolAddress((void**)&HD1, g_HD1);
    cudaGetSymbolAddress((void**)&HD2, g_HD2);

    prep_weights<<<1024, 256>>>(Uh, Wx, Wt, Wa, WxT, Wb, Wg, We, W1);
    prep_s<<<1, 512>>>(init_proj);
    prep_sA<<<1, 512>>>(Wa, We);
    prep_A<<<2048, 256>>>(inputs);

    // pre-GEMM (fp16): ZX(perm) + TG for all steps
    mma_gemm<5><<<dim3(20, 512), 256, SMEM_BYTES>>>(
        APRE, 64, 64, WPRE, b, nullptr, inputs, WtT, bT);

    for (int t = 0; t < 16; ++t) {
        if (t > 0) {
            // fp8: h_{t-1} @ [Uh|Wa|We] + fused gates -> Hc8, C, MEMA8/HWE slot t-1
            fp8_gemm<1><<<dim3(24, 32), 256, SMEM_BYTES>>>(
                Ah8 + (size_t)t * HSLOT, 512, WTb8,
                nullptr, Hc8,
                MEMA8 + (size_t)(t - 1) * HSLOT, HWE16 + (size_t)(t - 1) * HSLOT,
                nullptr, nullptr,
                ZX16 + (size_t)t * Bn * 2048, TG16 + (size_t)t * Bn * 512, C);
        } else {
            gates0_k<<<8192, 256>>>(ZX16, TG16, C, Hc8);
        }
        fp8_gemm<2><<<dim3(8, 32), 256, SMEM_BYTES>>>(
            Hc8, 512, WT28,
            ba, nullptr, nullptr, nullptr,
            HBh, HGh,
            nullptr, nullptr, nullptr);
        attn_k<<<4096, 256>>>(HBh, HGh, va, bh,
                              Ah8 + (size_t)(t + 1) * HSLOT, Ah16f, t);
    }

    mma_gemm<4><<<dim3(2, 32), 256, SMEM_BYTES>>>(
        Ah16f, 512, 512, WTh, b1, HD1, nullptr, nullptr, nullptr);
    head2_k<<<512, 256>>>(HD1, W2, b2, HD2);
    head3_k<<<16, 256>>>(HD2, W3, b3, out);
}

// round 16
// speedup vs baseline: 1.0367x; 1.0367x over previous
#include <cuda_runtime.h>
#include <cuda_fp16.h>
#include <cuda_fp8.h>
#include <math.h>
#include <stdint.h>

#define Bn 4096
#define HSLOT ((size_t)Bn * 512)
#define STAGE_BYTES 36864
#define SMEM_BYTES (3 * STAGE_BYTES)

// Gate permutation: physical col p (p<2048) <-> logical (gate g, unit j):
//   g = (p>>3)&3, j = ((p>>5)<<3) + (p&7)

// ---------------- device scratch ----------------
__device__ __half g_Ah[(size_t)17 * HSLOT];         // slot j+1 holds h_j (fp16); slot 0 unused
__device__ __half g_APRE[(size_t)65536 * 64];
__device__ __half g_WTb[(size_t)3072 * 512];        // [Uh(perm,2048) | Wa(512) | We(512)], n-major
__device__ __half g_WPRE[(size_t)2560 * 64];
__device__ __half g_WT2[1024 * 512];                // [Wb | Wg]
__device__ __half g_WTh[256 * 512];                 // W1
__device__ __half g_ZX16[(size_t)16 * Bn * 2048];
__device__ __half g_TG16[(size_t)16 * Bn * 512];
__device__ unsigned char g_MEMA8[(size_t)15 * HSLOT];  // slot j: h_j @ Wa, fp8 e4m3
__device__ __half g_HWE16[(size_t)15 * HSLOT];      // slot j: h_j @ We
__device__ __half g_HcH[(size_t)Bn * 512];
__device__ __half g_HBh[(size_t)Bn * 512];
__device__ __half g_HGh[(size_t)Bn * 512];
__device__ float g_C[(size_t)Bn * 512];
__device__ float g_HD1[(size_t)Bn * 256];
__device__ float g_HD2[(size_t)Bn * 32];
__device__ float g_s[512];
__device__ float g_sA[512];
__device__ float g_sWe[512];

__device__ __forceinline__ float sigm(float x) { return 1.f / (1.f + expf(-x)); }
__device__ __forceinline__ float sigmf_(float x) { return __fdividef(1.f, 1.f + __expf(-x)); }
__device__ __forceinline__ float tanh_app(float x) {
    float y; asm("tanh.approx.f32 %0, %1;" : "=f"(y) : "f"(x)); return y;
}

__device__ __forceinline__ uint32_t smem_u32(const void* p) {
    uint32_t a;
    asm("{ .reg .u64 t; cvta.to.shared.u64 t, %1; cvt.u32.u64 %0, t; }" : "=r"(a) : "l"(p));
    return a;
}
__device__ __forceinline__ void ldm4(uint32_t* r, uint32_t a) {
    asm volatile("ldmatrix.sync.aligned.m8n8.x4.shared.b16 {%0,%1,%2,%3}, [%4];"
                 : "=r"(r[0]), "=r"(r[1]), "=r"(r[2]), "=r"(r[3]) : "r"(a));
}
__device__ __forceinline__ void mma16816(float* c, const uint32_t* a, uint32_t b0, uint32_t b1) {
    asm volatile("mma.sync.aligned.m16n8k16.row.col.f32.f16.f16.f32 "
                 "{%0,%1,%2,%3}, {%4,%5,%6,%7}, {%8,%9}, {%0,%1,%2,%3};"
                 : "+f"(c[0]), "+f"(c[1]), "+f"(c[2]), "+f"(c[3])
                 : "r"(a[0]), "r"(a[1]), "r"(a[2]), "r"(a[3]), "r"(b0), "r"(b1));
}
__device__ __forceinline__ void cp16(uint32_t saddr, const void* gptr) {
    asm volatile("cp.async.cg.shared.global [%0], [%1], 16;"
                 :: "r"(saddr), "l"(__cvta_generic_to_global(gptr)) : "memory");
}
__device__ __forceinline__ void cp_commit() {
    asm volatile("cp.async.commit_group;" ::: "memory");
}

// PDL intrinsics (sm_90+): wait for upstream completion / signal downstream may launch
__device__ __forceinline__ void pdl_wait() {
    asm volatile("griddepcontrol.wait;" ::: "memory");
}
__device__ __forceinline__ void pdl_trigger() {
    asm volatile("griddepcontrol.launch_dependents;" ::: "memory");
}

// ---------------- prep kernels ----------------
__global__ void prep_weights(const float* __restrict__ Uh, const float* __restrict__ Wx,
                             const float* __restrict__ Wt, const float* __restrict__ Wa,
                             const float* __restrict__ WxT, const float* __restrict__ Wb,
                             const float* __restrict__ Wg, const float* __restrict__ We,
                             const float* __restrict__ W1) {
    int stride = gridDim.x * blockDim.x;
    int t0 = blockIdx.x * blockDim.x + threadIdx.x;
    for (int i = t0; i < 3072 * 512; i += stride) {
        int n = i >> 9, k = i & 511;
        float w;
        if (n < 2048) {
            int g = (n >> 3) & 3, j = ((n >> 5) << 3) + (n & 7);
            w = Uh[(size_t)k * 2048 + g * 512 + j];
        } else if (n < 2560) {
            w = Wa[(size_t)k * 512 + (n - 2048)];
        } else {
            w = We[(size_t)k * 512 + (n - 2560)];
        }
        g_WTb[i] = __float2half(w);
    }
    for (int i = t0; i < 2560 * 64; i += stride) {
        int n = i >> 6, k = i & 63;
        float w;
        if (n < 2048) {
            int g = (n >> 3) & 3, j = ((n >> 5) << 3) + (n & 7);
            if (k < 63) w = Wx[(size_t)k * 2048 + g * 512 + j];
            else        w = (g < 3) ? Wt[g * 512 + j] : 0.f;
        } else {
            w = (k < 63) ? WxT[(size_t)k * 512 + (n - 2048)] : 0.f;
        }
        g_WPRE[i] = __float2half(w);
    }
    for (int i = t0; i < 1024 * 512; i += stride) {
        int n = i >> 9, k = i & 511;
        float w = (n < 512) ? Wb[(size_t)k * 512 + n] : Wg[(size_t)k * 512 + (n - 512)];
        g_WT2[i] = __float2half(w);
    }
    for (int i = t0; i < 256 * 512; i += stride) {
        int n = i >> 9, k = i & 511;
        g_WTh[i] = __float2half(W1[(size_t)k * 256 + n]);
    }
}

__global__ void prep_s(const float* __restrict__ init_proj) {
    int h = threadIdx.x;
    float s = 0.f;
    for (int f = 0; f < 64; ++f) s += init_proj[f * 512 + h];
    g_s[h] = s;
}

__global__ void prep_sA(const float* __restrict__ Wa, const float* __restrict__ We) {
    int h = threadIdx.x;
    float a = 0.f, e = 0.f;
    for (int k = 0; k < 512; ++k) {
        float sv = g_s[k];
        a = fmaf(sv, Wa[k * 512 + h], a);
        e = fmaf(sv, We[k * 512 + h], e);
    }
    g_sA[h] = a;
    g_sWe[h] = e;
}

__global__ void prep_A(const float* __restrict__ inp) {
    int stride = gridDim.x * blockDim.x;
    int t0 = blockIdx.x * blockDim.x + threadIdx.x;
    for (int i = t0; i < 65536 * 64; i += stride) {
        int r = i >> 6, k = i & 63;
        float v = (k < 63) ? inp[(size_t)r * 64 + 1 + k] : inp[(size_t)r * 64];
        g_APRE[i] = __float2half(v);
    }
}

// ---------------- fp16 HMMA GEMM, 3-stage pipeline, PDL ----------------
// MODE 1: N=3072 [Uh(perm)|Wa|We]: n<2048 -> FUSED gates -> C, HcH(oh);
//         2048..2559 -> o2b (MEMA slot, fp8 e4m3); 2560..3071 -> o3h (HWE slot, fp16)
// MODE 2: N=1024 [Wb|Wg]: c<512 -> o2h=HBh(+e0); else oh=HGh
// MODE 4: N=256 W1: o0 = relu(acc+e0)
// MODE 5: N=2560 pre: c<2048 -> ZX16(perm); else TG16
template <int MODE>
__global__ __launch_bounds__(256, 2)
void mma_gemm(const __half* __restrict__ A, int lda, int K,
              const __half* __restrict__ Bh,
              const float* __restrict__ e0,
              float* __restrict__ o0,
              unsigned char* __restrict__ o2b, __half* __restrict__ o3h,
              __half* __restrict__ o2h, __half* __restrict__ oh,
              const __half* __restrict__ zxp, const __half* __restrict__ tgp,
              float* __restrict__ Cp,
              const float* __restrict__ inp, const float* __restrict__ WtT,
              const float* __restrict__ bT) {
    extern __shared__ char smem[];
    uint32_t sb = smem_u32(smem);
    const int tid = threadIdx.x;
    const int lane = tid & 31, wid = tid >> 5;
    const int wm = wid & 1, wn = wid >> 1;
    const int gid = lane >> 2, tq = lane & 3;
    const int m0 = blockIdx.y * 128, n0 = blockIdx.x * 128;

    const int kch = K >> 6;

    // wait for upstream kernel's results before reading A (weights are static but
    // A/zx/tg/C depend on predecessors in the step chain)
    pdl_wait();

    float acc[4][4][4];
    #pragma unroll
    for (int a = 0; a < 4; ++a)
        #pragma unroll
        for (int b2 = 0; b2 < 4; ++b2)
            #pragma unroll
            for (int c = 0; c < 4; ++c) acc[a][b2][c] = 0.f;

    auto copy_chunk = [&](int ch, int s) {
        int kc = ch << 6;
        uint32_t base = sb + s * STAGE_BYTES;
        #pragma unroll
        for (int i = 0; i < 4; ++i) {
            int lin = tid + (i << 8);
            int r = lin >> 3;
            int c16 = (lin & 7) << 4;
            cp16(base + r * 144 + c16,
                 (const char*)(A + (size_t)(m0 + r) * lda + kc) + c16);
            cp16(base + 18432 + r * 144 + c16,
                 (const char*)(Bh + (size_t)(n0 + r) * K + kc) + c16);
        }
    };

    copy_chunk(0, 0);
    cp_commit();
    if (kch > 1) { copy_chunk(1, 1); cp_commit(); }

    const int arow = wm * 64 + (lane & 15);
    const int acol = (lane >> 4) << 4;
    const int brow = wn * 32 + (lane & 7) + ((lane >> 4) << 3);
    const int bcol = ((lane >> 3) & 1) << 4;

    for (int ch = 0; ch < kch; ++ch) {
        if (ch + 1 < kch) {
            asm volatile("cp.async.wait_group 1;" ::: "memory");
        } else {
            asm volatile("cp.async.wait_group 0;" ::: "memory");
        }
        __syncthreads();

        int buf = ch % 3;
        uint32_t abase = sb + buf * STAGE_BYTES;
        uint32_t bbase = abase + 18432;
        #pragma unroll
        for (int k16 = 0; k16 < 4; ++k16) {
            int kb = k16 << 5;
            uint32_t bf[2][4];
            #pragma unroll
            for (int ni2 = 0; ni2 < 2; ++ni2)
                ldm4(bf[ni2], bbase + (brow + ni2 * 16) * 144 + kb + bcol);
            uint32_t af[4][4];
            #pragma unroll
            for (int mi = 0; mi < 4; ++mi)
                ldm4(af[mi], abase + (arow + mi * 16) * 144 + kb + acol);
            #pragma unroll
            for (int ni2 = 0; ni2 < 2; ++ni2)
                #pragma unroll
                for (int mi = 0; mi < 4; ++mi) {
                    mma16816(acc[mi][ni2 * 2],     af[mi], bf[ni2][0], bf[ni2][1]);
                    mma16816(acc[mi][ni2 * 2 + 1], af[mi], bf[ni2][2], bf[ni2][3]);
                }
        }
        if (ch + 2 < kch) {
            copy_chunk(ch + 2, (ch + 2) % 3);
            cp_commit();
        }
    }

    // let the dependent kernel's blocks launch while we run the epilogue
    pdl_trigger();

    // ---- epilogues ----
    if (MODE == 1) {
        if (n0 < 2048) {
            int blk = (n0 + wn * 32) >> 5;
            int j = blk * 8 + (tq << 1);
            #pragma unroll
            for (int mi = 0; mi < 4; ++mi) {
                int mb = m0 + wm * 64 + mi * 16 + gid;
                #pragma unroll
                for (int hf = 0; hf < 2; ++hf) {
                    int r = mb + hf * 8;
                    int ko = hf * 2;
                    const __half* zxr = zxp + (size_t)r * 2048 + blk * 32 + (tq << 1);
                    float2 xi = __half22float2(*(const __half2*)(zxr));
                    float2 xf = __half22float2(*(const __half2*)(zxr + 8));
                    float2 xo = __half22float2(*(const __half2*)(zxr + 16));
                    float2 xc = __half22float2(*(const __half2*)(zxr + 24));
                    float2 tg2 = __half22float2(*(const __half2*)(tgp + (size_t)r * 512 + j));
                    float2 cold = *(float2*)(Cp + (size_t)r * 512 + j);
                    float ch0 = tanh_app(acc[mi][3][ko] + xc.x);
                    float ch1 = tanh_app(acc[mi][3][ko + 1] + xc.y);
                    float c0 = fmaf(sigmf_(acc[mi][1][ko] + xf.x), cold.x,
                                    (sigmf_(acc[mi][0][ko] + xi.x) + tg2.x) * ch0);
                    float c1 = fmaf(sigmf_(acc[mi][1][ko + 1] + xf.y), cold.y,
                                    (sigmf_(acc[mi][0][ko + 1] + xi.y) + tg2.y) * ch1);
                    *(float2*)(Cp + (size_t)r * 512 + j) = make_float2(c0, c1);
                    float h0 = sigmf_(acc[mi][2][ko] + xo.x) * tanh_app(c0);
                    float h1 = sigmf_(acc[mi][2][ko + 1] + xo.y) * tanh_app(c1);
                    *(__half2*)(oh + (size_t)r * 512 + j) = __floats2half2_rn(h0, h1);
                }
            }
        } else if (n0 < 2560) {
            #pragma unroll
            for (int mi = 0; mi < 4; ++mi)
                #pragma unroll
                for (int ni = 0; ni < 4; ++ni) {
                    float* cc = acc[mi][ni];
                    int m = m0 + wm * 64 + mi * 16 + gid;
                    int c = n0 + wn * 32 + ni * 8 + (tq << 1) - 2048;
                    __nv_fp8x2_storage_t p0 = __nv_cvt_float2_to_fp8x2(
                        make_float2(cc[0], cc[1]), __NV_SATFINITE, __NV_E4M3);
                    __nv_fp8x2_storage_t p1 = __nv_cvt_float2_to_fp8x2(
                        make_float2(cc[2], cc[3]), __NV_SATFINITE, __NV_E4M3);
                    *(__nv_fp8x2_storage_t*)(o2b + (size_t)m * 512 + c) = p0;
                    *(__nv_fp8x2_storage_t*)(o2b + (size_t)(m + 8) * 512 + c) = p1;
                }
        } else {
            #pragma unroll
            for (int mi = 0; mi < 4; ++mi)
                #pragma unroll
                for (int ni = 0; ni < 4; ++ni) {
                    float* cc = acc[mi][ni];
                    int m = m0 + wm * 64 + mi * 16 + gid;
                    int c = n0 + wn * 32 + ni * 8 + (tq << 1) - 2560;
                    *(__half2*)(o3h + (size_t)m * 512 + c) = __floats2half2_rn(cc[0], cc[1]);
                    *(__half2*)(o3h + (size_t)(m + 8) * 512 + c) = __floats2half2_rn(cc[2], cc[3]);
                }
        }
        return;
    }

    auto epi = [&](int m, int c, float x, float y) {
        if (MODE == 2) {
            if (c < 512) {
                *(__half2*)(o2h + (size_t)m * 512 + c) =
                    __floats2half2_rn(x + e0[c], y + e0[c + 1]);
            } else {
                *(__half2*)(oh + (size_t)m * 512 + (c - 512)) = __floats2half2_rn(x, y);
            }
        } else if (MODE == 4) {
            *(float2*)(o0 + (size_t)m * 256 + c) =
                make_float2(fmaxf(x + e0[c], 0.f), fmaxf(y + e0[c + 1], 0.f));
        } else {  // MODE 5
            int b_ = m >> 4, t_ = m & 15;
            size_t zr = (size_t)t_ * Bn + b_;
            if (c < 2048) {
                int g = (c >> 3) & 3;
                int j0 = ((c >> 5) << 3) + (c & 7);
                *(__half2*)(g_ZX16 + zr * 2048 + c) =
                    __floats2half2_rn(x + e0[g * 512 + j0], y + e0[g * 512 + j0 + 1]);
            } else {
                int j = c - 2048;
                float tv = inp[(size_t)m * 64];
                float t0v = sigm(x + sigm(tv * WtT[j]) + bT[j]);
                float t1v = sigm(y + sigm(tv * WtT[j + 1]) + bT[j + 1]);
                *(__half2*)(g_TG16 + zr * 512 + j) = __floats2half2_rn(t0v, t1v);
            }
        }
    };

    #pragma unroll
    for (int mi = 0; mi < 4; ++mi) {
        #pragma unroll
        for (int ni = 0; ni < 4; ++ni) {
            float* cc = acc[mi][ni];
            int m = m0 + wm * 64 + mi * 16 + gid;
            int c = n0 + wn * 32 + ni * 8 + (tq << 1);
            epi(m, c, cc[0], cc[1]);
            epi(m + 8, c, cc[2], cc[3]);
        }
    }
}

// ---------------- t=0 gates ----------------
__global__ void gates0_k(const __half* __restrict__ ZX, const __half* __restrict__ TG,
                         float* __restrict__ C, __half* __restrict__ HcH) {
    pdl_wait();
    int idx = blockIdx.x * blockDim.x + threadIdx.x;
    int b = idx >> 9, j = idx & 511;
    int blk = j >> 3, jr = j & 7;
    const __half* zx = ZX + (size_t)b * 2048 + blk * 32 + jr;
    float zi = __half2float(zx[0]);
    float zo = __half2float(zx[16]);
    float zc = __half2float(zx[24]);
    float tg = __half2float(TG[idx]);
    float ch = tanh_app(zc);
    float c = (sigmf_(zi) + tg) * ch;
    C[idx] = c;
    HcH[idx] = __float2half(sigmf_(zo) * tanh_app(c));
    pdl_trigger();
}

// ---------------- attention + h_new epilogue (fp8 MEMA, fp16 HWE) ----------------
__global__ void __launch_bounds__(256) attn_k(const __half* __restrict__ HB,
                                              const __half* __restrict__ HG,
                                              const float* __restrict__ va,
                                              const float* __restrict__ bhv,
                                              __half* __restrict__ AhNext, int t) {
    int b = blockIdx.x, tid = threadIdx.x;
    __shared__ float sred[15][8];
    __shared__ float se[15];
    pdl_wait();
    float2 hb = __half22float2(((const __half2*)(HB + (size_t)b * 512))[tid]);
    float2 va2 = *(const float2*)(va + 2 * tid);
    float2 sA2 = *(const float2*)(g_sA + 2 * tid);
    float2 sW2 = *(const float2*)(g_sWe + 2 * tid);
    int lane = tid & 31, wp = tid >> 5;

    #pragma unroll
    for (int d = 0; d < 15; ++d) {
        int j = t - 15 + d;
        float m0, m1;
        if (j < 0) {
            m0 = sA2.x; m1 = sA2.y;
        } else {
            __nv_fp8x2_storage_t raw =
                ((const __nv_fp8x2_storage_t*)(g_MEMA8 + (size_t)j * HSLOT + (size_t)b * 512))[tid];
            __half2_raw hr = __nv_cvt_fp8x2_to_halfraw2(raw, __NV_E4M3);
            float2 f = __half22float2(*(__half2*)&hr);
            m0 = f.x; m1 = f.y;
        }
        float s = va2.x * tanh_app(m0 + hb.x) + va2.y * tanh_app(m1 + hb.y);
        #pragma unroll
        for (int off = 16; off; off >>= 1) s += __shfl_xor_sync(0xffffffffu, s, off);
        if (lane == 0) sred[d][wp] = s;
    }
    __syncthreads();
    if (tid < 15) {
        float e = 0.f;
        #pragma unroll
        for (int w2 = 0; w2 < 8; ++w2) e += sred[tid][w2];
        se[tid] = e;
    }
    __syncthreads();

    float mx = -1e30f;
    #pragma unroll
    for (int d = 0; d < 15; ++d) mx = fmaxf(mx, se[d]);
    float al[15], sum = 0.f;
    #pragma unroll
    for (int d = 0; d < 15; ++d) { al[d] = __expf(se[d] - mx); sum += al[d]; }
    float inv = __fdividef(1.f, sum);
    float c0 = 0.f, c1 = 0.f;
    #pragma unroll
    for (int d = 0; d < 15; ++d) {
        int j = t - 15 + d;
        float a = al[d] * inv;
        float m0, m1;
        if (j < 0) {
            m0 = sW2.x; m1 = sW2.y;
        } else {
            float2 f = __half22float2(
                ((const __half2*)(g_HWE16 + (size_t)j * HSLOT + (size_t)b * 512))[tid]);
            m0 = f.x; m1 = f.y;
        }
        c0 = fmaf(a, m0, c0);
        c1 = fmaf(a, m1, c1);
    }
    float2 hg = __half22float2(((const __half2*)(HG + (size_t)b * 512))[tid]);
    float2 bh2 = *(const float2*)(bhv + 2 * tid);
    float h0 = tanh_app(c0 + hg.x + bh2.x);
    float h1 = tanh_app(c1 + hg.y + bh2.y);
    pdl_trigger();
    ((__half2*)(AhNext + (size_t)b * 512))[tid] = __floats2half2_rn(h0, h1);
}

// ---------------- head layers 2,3 ----------------
__global__ void head2_k(const float* __restrict__ HD1, const float* __restrict__ W2,
                        const float* __restrict__ b2, float* __restrict__ HD2) {
    int warp = (blockIdx.x * blockDim.x + threadIdx.x) >> 5;
    int lane = threadIdx.x & 31;
    if (warp >= Bn) return;
    const float* h = HD1 + (size_t)warp * 256;
    float acc = 0.f;
    for (int k = 0; k < 256; ++k) acc = fmaf(h[k], W2[k * 32 + lane], acc);
    HD2[(size_t)warp * 32 + lane] = fmaxf(acc + b2[lane], 0.f);
}

__global__ void head3_k(const float* __restrict__ HD2, const float* __restrict__ W3,
                        const float* __restrict__ b3, float* __restrict__ out) {
    int b = blockIdx.x * blockDim.x + threadIdx.x;
    if (b >= Bn) return;
    float a0 = b3[0], a1 = b3[1];
    const float* h = HD2 + (size_t)b * 32;
    #pragma unroll
    for (int k = 0; k < 32; ++k) {
        float hv = h[k];
        a0 = fmaf(hv, W3[k * 2 + 0], a0);
        a1 = fmaf(hv, W3[k * 2 + 1], a1);
    }
    float m = fmaxf(a0, a1);
    float e0v = expf(a0 - m), e1v = expf(a1 - m);
    float inv = 1.f / (e0v + e1v);
    out[(size_t)b * 2 + 0] = e0v * inv;
    out[(size_t)b * 2 + 1] = e1v * inv;
}

// ---------------- PDL launch helper ----------------
template <typename F, typename... Args>
static inline void launch_pdl(F f, dim3 grid, dim3 block, size_t smem, Args... args) {
    cudaLaunchConfig_t cfg = {};
    cfg.gridDim = grid;
    cfg.blockDim = block;
    cfg.dynamicSmemBytes = smem;
    cfg.stream = 0;
    cudaLaunchAttribute attr[1];
    attr[0].id = cudaLaunchAttributeProgrammaticStreamSerialization;
    attr[0].val.programmaticStreamSerializationAllowed = 1;
    cfg.attrs = attr;
    cfg.numAttrs = 1;
    cudaLaunchKernelEx(&cfg, f, args...);
}

// ---------------- launcher ----------------
extern "C" void kernel_launch(void* const* d_in, const int* in_sizes, int n_in,
                              void* d_out, int out_size) {
    const float* inputs    = (const float*)d_in[0];
    const float* init_proj = (const float*)d_in[1];
    const float* Wx  = (const float*)d_in[3];
    const float* Uh  = (const float*)d_in[4];
    const float* Wt  = (const float*)d_in[5];
    const float* b   = (const float*)d_in[6];
    const float* WxT = (const float*)d_in[7];
    const float* WtT = (const float*)d_in[8];
    const float* bT  = (const float*)d_in[9];
    const float* Wa  = (const float*)d_in[10];
    const float* Wb  = (const float*)d_in[11];
    const float* va  = (const float*)d_in[12];
    const float* ba  = (const float*)d_in[13];
    const float* We  = (const float*)d_in[14];
    const float* Wg  = (const float*)d_in[15];
    const float* bh  = (const float*)d_in[16];
    const float* W1  = (const float*)d_in[17];
    const float* b1  = (const float*)d_in[18];
    const float* W2  = (const float*)d_in[19];
    const float* b2  = (const float*)d_in[20];
    const float* W3  = (const float*)d_in[21];
    const float* b3  = (const float*)d_in[22];
    float* out = (float*)d_out;

    cudaFuncSetAttribute(mma_gemm<1>, cudaFuncAttributeMaxDynamicSharedMemorySize, SMEM_BYTES);
    cudaFuncSetAttribute(mma_gemm<2>, cudaFuncAttributeMaxDynamicSharedMemorySize, SMEM_BYTES);
    cudaFuncSetAttribute(mma_gemm<4>, cudaFuncAttributeMaxDynamicSharedMemorySize, SMEM_BYTES);
    cudaFuncSetAttribute(mma_gemm<5>, cudaFuncAttributeMaxDynamicSharedMemorySize, SMEM_BYTES);

    __half *Ah, *APRE, *WTb, *WPRE, *WT2, *WTh, *HWE16, *ZX16, *TG16, *HcH, *HBh, *HGh;
    unsigned char* MEMA8;
    float *C, *HD1, *HD2;
    cudaGetSymbolAddress((void**)&Ah, g_Ah);
    cudaGetSymbolAddress((void**)&APRE, g_APRE);
    cudaGetSymbolAddress((void**)&WTb, g_WTb);
    cudaGetSymbolAddress((void**)&WPRE, g_WPRE);
    cudaGetSymbolAddress((void**)&WT2, g_WT2);
    cudaGetSymbolAddress((void**)&WTh, g_WTh);
    cudaGetSymbolAddress((void**)&MEMA8, g_MEMA8);
    cudaGetSymbolAddress((void**)&HWE16, g_HWE16);
    cudaGetSymbolAddress((void**)&ZX16, g_ZX16);
    cudaGetSymbolAddress((void**)&TG16, g_TG16);
    cudaGetSymbolAddress((void**)&HcH, g_HcH);
    cudaGetSymbolAddress((void**)&HBh, g_HBh);
    cudaGetSymbolAddress((void**)&HGh, g_HGh);
    cudaGetSymbolAddress((void**)&C, g_C);
    cudaGetSymbolAddress((void**)&HD1, g_HD1);
    cudaGetSymbolAddress((void**)&HD2, g_HD2);

    prep_weights<<<1024, 256>>>(Uh, Wx, Wt, Wa, WxT, Wb, Wg, We, W1);
    prep_s<<<1, 512>>>(init_proj);
    prep_sA<<<1, 512>>>(Wa, We);
    prep_A<<<2048, 256>>>(inputs);

    // pre-GEMM: ZX(perm) + TG for all steps
    mma_gemm<5><<<dim3(20, 512), 256, SMEM_BYTES>>>(
        APRE, 64, 64, WPRE,
        b, (float*)nullptr,
        (unsigned char*)nullptr, (__half*)nullptr, (__half*)nullptr, (__half*)nullptr,
        (const __half*)nullptr, (const __half*)nullptr, (float*)nullptr,
        inputs, WtT, bT);

    for (int t = 0; t < 16; ++t) {
        if (t > 0) {
            launch_pdl(mma_gemm<1>, dim3(24, 32), dim3(256), (size_t)SMEM_BYTES,
                (const __half*)(Ah + (size_t)t * HSLOT), 512, 512,
                (const __half*)WTb,
                (const float*)nullptr, (float*)nullptr,
                (unsigned char*)(MEMA8 + (size_t)(t - 1) * HSLOT),
                (__half*)(HWE16 + (size_t)(t - 1) * HSLOT),
                (__half*)nullptr, (__half*)HcH,
                (const __half*)(ZX16 + (size_t)t * Bn * 2048),
                (const __half*)(TG16 + (size_t)t * Bn * 512),
                (float*)C,
                (const float*)nullptr, (const float*)nullptr, (const float*)nullptr);
        } else {
            launch_pdl(gates0_k, dim3(8192), dim3(256), (size_t)0,
                (const __half*)ZX16, (const __half*)TG16, (float*)C, (__half*)HcH);
        }
        launch_pdl(mma_gemm<2>, dim3(8, 32), dim3(256), (size_t)SMEM_BYTES,
            (const __half*)HcH, 512, 512,
            (const __half*)WT2,
            (const float*)ba, (float*)nullptr,
            (unsigned char*)nullptr, (__half*)nullptr,
            (__half*)HBh, (__half*)HGh,
            (const __half*)nullptr, (const __half*)nullptr, (float*)nullptr,
            (const float*)nullptr, (const float*)nullptr, (const float*)nullptr);
        launch_pdl(attn_k, dim3(4096), dim3(256), (size_t)0,
            (const __half*)HBh, (const __half*)HGh,
            (const float*)va, (const float*)bh,
            (__half*)(Ah + (size_t)(t + 1) * HSLOT), t);
    }

    mma_gemm<4><<<dim3(2, 32), 256, SMEM_BYTES>>>(
        Ah + (size_t)16 * HSLOT, 512, 512, WTh,
        b1, HD1,
        (unsigned char*)nullptr, (__half*)nullptr, (__half*)nullptr, (__half*)nullptr,
        (const __half*)nullptr, (const __half*)nullptr, (float*)nullptr,
        (const float*)nullptr, (const float*)nullptr, (const float*)nullptr);
    head2_k<<<512, 256>>>(HD1, W2, b2, HD2);
    head3_k<<<16, 256>>>(HD2, W3, b3, out);
}

// round 17
// speedup vs baseline: 1.0387x; 1.0019x over previous
#include <cuda_runtime.h>
#include <cuda_fp16.h>
#include <cuda_fp8.h>
#include <math.h>
#include <stdint.h>

#define Bn 4096
#define HSLOT ((size_t)Bn * 512)
#define STAGE_BYTES 36864
#define SMEM_BYTES (3 * STAGE_BYTES)

// Gate permutation: physical col p (p<2048) <-> logical (gate g, unit j):
//   g = (p>>3)&3, j = ((p>>5)<<3) + (p&7)

// ---------------- device scratch ----------------
__device__ __half g_Ah[(size_t)17 * HSLOT];         // slot j+1 holds h_j (fp16); slot 0 unused
__device__ __half g_APRE[(size_t)65536 * 64];
__device__ __half g_WTb[(size_t)3072 * 512];        // [Uh(perm,2048) | Wa(512) | We(512)], n-major
__device__ __half g_WPRE[(size_t)2560 * 64];
__device__ __half g_WT2[1024 * 512];                // [Wb | Wg]
__device__ __half g_WTh[256 * 512];                 // W1
__device__ __half g_ZX16[(size_t)16 * Bn * 2048];
__device__ __half g_TG16[(size_t)16 * Bn * 512];
__device__ unsigned char g_MEMA8[(size_t)15 * HSLOT];  // slot j: h_j @ Wa, fp8 e4m3
__device__ unsigned char g_HWE8[(size_t)15 * HSLOT];   // slot j: h_j @ We, fp8 e4m3
__device__ __half g_HcH[(size_t)Bn * 512];
__device__ __half g_HBh[(size_t)Bn * 512];
__device__ __half g_HGh[(size_t)Bn * 512];
__device__ float g_C[(size_t)Bn * 512];
__device__ float g_HD1[(size_t)Bn * 256];
__device__ float g_HD2[(size_t)Bn * 32];
__device__ float g_s[512];
__device__ float g_sA[512];
__device__ float g_sWe[512];

__device__ __forceinline__ float sigm(float x) { return 1.f / (1.f + expf(-x)); }
__device__ __forceinline__ float sigmf_(float x) { return __fdividef(1.f, 1.f + __expf(-x)); }
__device__ __forceinline__ float tanh_app(float x) {
    float y; asm("tanh.approx.f32 %0, %1;" : "=f"(y) : "f"(x)); return y;
}

__device__ __forceinline__ uint32_t smem_u32(const void* p) {
    uint32_t a;
    asm("{ .reg .u64 t; cvta.to.shared.u64 t, %1; cvt.u32.u64 %0, t; }" : "=r"(a) : "l"(p));
    return a;
}
__device__ __forceinline__ void ldm4(uint32_t* r, uint32_t a) {
    asm volatile("ldmatrix.sync.aligned.m8n8.x4.shared.b16 {%0,%1,%2,%3}, [%4];"
                 : "=r"(r[0]), "=r"(r[1]), "=r"(r[2]), "=r"(r[3]) : "r"(a));
}
__device__ __forceinline__ void mma16816(float* c, const uint32_t* a, uint32_t b0, uint32_t b1) {
    asm volatile("mma.sync.aligned.m16n8k16.row.col.f32.f16.f16.f32 "
                 "{%0,%1,%2,%3}, {%4,%5,%6,%7}, {%8,%9}, {%0,%1,%2,%3};"
                 : "+f"(c[0]), "+f"(c[1]), "+f"(c[2]), "+f"(c[3])
                 : "r"(a[0]), "r"(a[1]), "r"(a[2]), "r"(a[3]), "r"(b0), "r"(b1));
}
__device__ __forceinline__ void cp16(uint32_t saddr, const void* gptr) {
    asm volatile("cp.async.cg.shared.global [%0], [%1], 16;"
                 :: "r"(saddr), "l"(__cvta_generic_to_global(gptr)) : "memory");
}
__device__ __forceinline__ void cp_commit() {
    asm volatile("cp.async.commit_group;" ::: "memory");
}
__device__ __forceinline__ __nv_fp8x2_storage_t f2_to_fp8x2(float x, float y) {
    return __nv_cvt_float2_to_fp8x2(make_float2(x, y), __NV_SATFINITE, __NV_E4M3);
}
__device__ __forceinline__ float2 fp8x2_to_f2(__nv_fp8x2_storage_t raw) {
    __half2_raw hr = __nv_cvt_fp8x2_to_halfraw2(raw, __NV_E4M3);
    return __half22float2(*(__half2*)&hr);
}

// PDL intrinsics (sm_90+)
__device__ __forceinline__ void pdl_wait() {
    asm volatile("griddepcontrol.wait;" ::: "memory");
}
__device__ __forceinline__ void pdl_trigger() {
    asm volatile("griddepcontrol.launch_dependents;" ::: "memory");
}

// ---------------- prep kernels ----------------
__global__ void prep_weights(const float* __restrict__ Uh, const float* __restrict__ Wx,
                             const float* __restrict__ Wt, const float* __restrict__ Wa,
                             const float* __restrict__ WxT, const float* __restrict__ Wb,
                             const float* __restrict__ Wg, const float* __restrict__ We,
                             const float* __restrict__ W1) {
    int stride = gridDim.x * blockDim.x;
    int t0 = blockIdx.x * blockDim.x + threadIdx.x;
    for (int i = t0; i < 3072 * 512; i += stride) {
        int n = i >> 9, k = i & 511;
        float w;
        if (n < 2048) {
            int g = (n >> 3) & 3, j = ((n >> 5) << 3) + (n & 7);
            w = Uh[(size_t)k * 2048 + g * 512 + j];
        } else if (n < 2560) {
            w = Wa[(size_t)k * 512 + (n - 2048)];
        } else {
            w = We[(size_t)k * 512 + (n - 2560)];
        }
        g_WTb[i] = __float2half(w);
    }
    for (int i = t0; i < 2560 * 64; i += stride) {
        int n = i >> 6, k = i & 63;
        float w;
        if (n < 2048) {
            int g = (n >> 3) & 3, j = ((n >> 5) << 3) + (n & 7);
            if (k < 63) w = Wx[(size_t)k * 2048 + g * 512 + j];
            else        w = (g < 3) ? Wt[g * 512 + j] : 0.f;
        } else {
            w = (k < 63) ? WxT[(size_t)k * 512 + (n - 2048)] : 0.f;
        }
        g_WPRE[i] = __float2half(w);
    }
    for (int i = t0; i < 1024 * 512; i += stride) {
        int n = i >> 9, k = i & 511;
        float w = (n < 512) ? Wb[(size_t)k * 512 + n] : Wg[(size_t)k * 512 + (n - 512)];
        g_WT2[i] = __float2half(w);
    }
    for (int i = t0; i < 256 * 512; i += stride) {
        int n = i >> 9, k = i & 511;
        g_WTh[i] = __float2half(W1[(size_t)k * 256 + n]);
    }
}

__global__ void prep_s(const float* __restrict__ init_proj) {
    int h = threadIdx.x;
    float s = 0.f;
    for (int f = 0; f < 64; ++f) s += init_proj[f * 512 + h];
    g_s[h] = s;
}

__global__ void prep_sA(const float* __restrict__ Wa, const float* __restrict__ We) {
    int h = threadIdx.x;
    float a = 0.f, e = 0.f;
    for (int k = 0; k < 512; ++k) {
        float sv = g_s[k];
        a = fmaf(sv, Wa[k * 512 + h], a);
        e = fmaf(sv, We[k * 512 + h], e);
    }
    g_sA[h] = a;
    g_sWe[h] = e;
}

__global__ void prep_A(const float* __restrict__ inp) {
    int stride = gridDim.x * blockDim.x;
    int t0 = blockIdx.x * blockDim.x + threadIdx.x;
    for (int i = t0; i < 65536 * 64; i += stride) {
        int r = i >> 6, k = i & 63;
        float v = (k < 63) ? inp[(size_t)r * 64 + 1 + k] : inp[(size_t)r * 64];
        g_APRE[i] = __float2half(v);
    }
}

// ---------------- fp16 HMMA GEMM, 3-stage pipeline, PDL ----------------
// MODE 1: N=3072 [Uh(perm)|Wa|We]: n<2048 -> FUSED gates -> C, HcH(oh);
//         2048..2559 -> MEMA8 (o2b); 2560..3071 -> HWE8 (o3b), both fp8 e4m3
// MODE 2: N=1024 [Wb|Wg]: c<512 -> o2h=HBh(+e0); else oh=HGh
// MODE 4: N=256 W1: o0 = relu(acc+e0)
// MODE 5: N=2560 pre: c<2048 -> ZX16(perm); else TG16
template <int MODE>
__global__ __launch_bounds__(256, 2)
void mma_gemm(const __half* __restrict__ A, int lda, int K,
              const __half* __restrict__ Bh,
              const float* __restrict__ e0,
              float* __restrict__ o0,
              unsigned char* __restrict__ o2b, unsigned char* __restrict__ o3b,
              __half* __restrict__ o2h, __half* __restrict__ oh,
              const __half* __restrict__ zxp, const __half* __restrict__ tgp,
              float* __restrict__ Cp,
              const float* __restrict__ inp, const float* __restrict__ WtT,
              const float* __restrict__ bT) {
    extern __shared__ char smem[];
    uint32_t sb = smem_u32(smem);
    const int tid = threadIdx.x;
    const int lane = tid & 31, wid = tid >> 5;
    const int wm = wid & 1, wn = wid >> 1;
    const int gid = lane >> 2, tq = lane & 3;
    const int m0 = blockIdx.y * 128, n0 = blockIdx.x * 128;

    const int kch = K >> 6;

    pdl_wait();

    float acc[4][4][4];
    #pragma unroll
    for (int a = 0; a < 4; ++a)
        #pragma unroll
        for (int b2 = 0; b2 < 4; ++b2)
            #pragma unroll
            for (int c = 0; c < 4; ++c) acc[a][b2][c] = 0.f;

    auto copy_chunk = [&](int ch, int s) {
        int kc = ch << 6;
        uint32_t base = sb + s * STAGE_BYTES;
        #pragma unroll
        for (int i = 0; i < 4; ++i) {
            int lin = tid + (i << 8);
            int r = lin >> 3;
            int c16 = (lin & 7) << 4;
            cp16(base + r * 144 + c16,
                 (const char*)(A + (size_t)(m0 + r) * lda + kc) + c16);
            cp16(base + 18432 + r * 144 + c16,
                 (const char*)(Bh + (size_t)(n0 + r) * K + kc) + c16);
        }
    };

    copy_chunk(0, 0);
    cp_commit();
    if (kch > 1) { copy_chunk(1, 1); cp_commit(); }

    const int arow = wm * 64 + (lane & 15);
    const int acol = (lane >> 4) << 4;
    const int brow = wn * 32 + (lane & 7) + ((lane >> 4) << 3);
    const int bcol = ((lane >> 3) & 1) << 4;

    for (int ch = 0; ch < kch; ++ch) {
        if (ch + 1 < kch) {
            asm volatile("cp.async.wait_group 1;" ::: "memory");
        } else {
            asm volatile("cp.async.wait_group 0;" ::: "memory");
        }
        __syncthreads();

        int buf = ch % 3;
        uint32_t abase = sb + buf * STAGE_BYTES;
        uint32_t bbase = abase + 18432;
        #pragma unroll
        for (int k16 = 0; k16 < 4; ++k16) {
            int kb = k16 << 5;
            uint32_t bf[2][4];
            #pragma unroll
            for (int ni2 = 0; ni2 < 2; ++ni2)
                ldm4(bf[ni2], bbase + (brow + ni2 * 16) * 144 + kb + bcol);
            uint32_t af[4][4];
            #pragma unroll
            for (int mi = 0; mi < 4; ++mi)
                ldm4(af[mi], abase + (arow + mi * 16) * 144 + kb + acol);
            #pragma unroll
            for (int ni2 = 0; ni2 < 2; ++ni2)
                #pragma unroll
                for (int mi = 0; mi < 4; ++mi) {
                    mma16816(acc[mi][ni2 * 2],     af[mi], bf[ni2][0], bf[ni2][1]);
                    mma16816(acc[mi][ni2 * 2 + 1], af[mi], bf[ni2][2], bf[ni2][3]);
                }
        }
        if (ch + 2 < kch) {
            copy_chunk(ch + 2, (ch + 2) % 3);
            cp_commit();
        }
    }

    pdl_trigger();

    // ---- epilogues ----
    if (MODE == 1) {
        if (n0 < 2048) {
            int blk = (n0 + wn * 32) >> 5;
            int j = blk * 8 + (tq << 1);
            #pragma unroll
            for (int mi = 0; mi < 4; ++mi) {
                int mb = m0 + wm * 64 + mi * 16 + gid;
                #pragma unroll
                for (int hf = 0; hf < 2; ++hf) {
                    int r = mb + hf * 8;
                    int ko = hf * 2;
                    const __half* zxr = zxp + (size_t)r * 2048 + blk * 32 + (tq << 1);
                    float2 xi = __half22float2(*(const __half2*)(zxr));
                    float2 xf = __half22float2(*(const __half2*)(zxr + 8));
                    float2 xo = __half22float2(*(const __half2*)(zxr + 16));
                    float2 xc = __half22float2(*(const __half2*)(zxr + 24));
                    float2 tg2 = __half22float2(*(const __half2*)(tgp + (size_t)r * 512 + j));
                    float2 cold = *(float2*)(Cp + (size_t)r * 512 + j);
                    float ch0 = tanh_app(acc[mi][3][ko] + xc.x);
                    float ch1 = tanh_app(acc[mi][3][ko + 1] + xc.y);
                    float c0 = fmaf(sigmf_(acc[mi][1][ko] + xf.x), cold.x,
                                    (sigmf_(acc[mi][0][ko] + xi.x) + tg2.x) * ch0);
                    float c1 = fmaf(sigmf_(acc[mi][1][ko + 1] + xf.y), cold.y,
                                    (sigmf_(acc[mi][0][ko + 1] + xi.y) + tg2.y) * ch1);
                    *(float2*)(Cp + (size_t)r * 512 + j) = make_float2(c0, c1);
                    float h0 = sigmf_(acc[mi][2][ko] + xo.x) * tanh_app(c0);
                    float h1 = sigmf_(acc[mi][2][ko + 1] + xo.y) * tanh_app(c1);
                    *(__half2*)(oh + (size_t)r * 512 + j) = __floats2half2_rn(h0, h1);
                }
            }
        } else {
            unsigned char* dst = (n0 < 2560) ? o2b : o3b;
            int base = (n0 < 2560) ? 2048 : 2560;
            #pragma unroll
            for (int mi = 0; mi < 4; ++mi)
                #pragma unroll
                for (int ni = 0; ni < 4; ++ni) {
                    float* cc = acc[mi][ni];
                    int m = m0 + wm * 64 + mi * 16 + gid;
                    int c = n0 + wn * 32 + ni * 8 + (tq << 1) - base;
                    *(__nv_fp8x2_storage_t*)(dst + (size_t)m * 512 + c) = f2_to_fp8x2(cc[0], cc[1]);
                    *(__nv_fp8x2_storage_t*)(dst + (size_t)(m + 8) * 512 + c) = f2_to_fp8x2(cc[2], cc[3]);
                }
        }
        return;
    }

    auto epi = [&](int m, int c, float x, float y) {
        if (MODE == 2) {
            if (c < 512) {
                *(__half2*)(o2h + (size_t)m * 512 + c) =
                    __floats2half2_rn(x + e0[c], y + e0[c + 1]);
            } else {
                *(__half2*)(oh + (size_t)m * 512 + (c - 512)) = __floats2half2_rn(x, y);
            }
        } else if (MODE == 4) {
            *(float2*)(o0 + (size_t)m * 256 + c) =
                make_float2(fmaxf(x + e0[c], 0.f), fmaxf(y + e0[c + 1], 0.f));
        } else {  // MODE 5
            int b_ = m >> 4, t_ = m & 15;
            size_t zr = (size_t)t_ * Bn + b_;
            if (c < 2048) {
                int g = (c >> 3) & 3;
                int j0 = ((c >> 5) << 3) + (c & 7);
                *(__half2*)(g_ZX16 + zr * 2048 + c) =
                    __floats2half2_rn(x + e0[g * 512 + j0], y + e0[g * 512 + j0 + 1]);
            } else {
                int j = c - 2048;
                float tv = inp[(size_t)m * 64];
                float t0v = sigm(x + sigm(tv * WtT[j]) + bT[j]);
                float t1v = sigm(y + sigm(tv * WtT[j + 1]) + bT[j + 1]);
                *(__half2*)(g_TG16 + zr * 512 + j) = __floats2half2_rn(t0v, t1v);
            }
        }
    };

    #pragma unroll
    for (int mi = 0; mi < 4; ++mi) {
        #pragma unroll
        for (int ni = 0; ni < 4; ++ni) {
            float* cc = acc[mi][ni];
            int m = m0 + wm * 64 + mi * 16 + gid;
            int c = n0 + wn * 32 + ni * 8 + (tq << 1);
            epi(m, c, cc[0], cc[1]);
            epi(m + 8, c, cc[2], cc[3]);
        }
    }
}

// ---------------- t=0 gates ----------------
__global__ void gates0_k(const __half* __restrict__ ZX, const __half* __restrict__ TG,
                         float* __restrict__ C, __half* __restrict__ HcH) {
    pdl_wait();
    int idx = blockIdx.x * blockDim.x + threadIdx.x;
    int b = idx >> 9, j = idx & 511;
    int blk = j >> 3, jr = j & 7;
    const __half* zx = ZX + (size_t)b * 2048 + blk * 32 + jr;
    float zi = __half2float(zx[0]);
    float zo = __half2float(zx[16]);
    float zc = __half2float(zx[24]);
    float tg = __half2float(TG[idx]);
    float ch = tanh_app(zc);
    float c = (sigmf_(zi) + tg) * ch;
    C[idx] = c;
    HcH[idx] = __float2half(sigmf_(zo) * tanh_app(c));
    pdl_trigger();
}

// ---------------- attention + h_new epilogue (fp8 MEMA + fp8 HWE) ----------------
__global__ void __launch_bounds__(256) attn_k(const __half* __restrict__ HB,
                                              const __half* __restrict__ HG,
                                              const float* __restrict__ va,
                                              const float* __restrict__ bhv,
                                              __half* __restrict__ AhNext, int t) {
    int b = blockIdx.x, tid = threadIdx.x;
    __shared__ float sred[15][8];
    __shared__ float se[15];
    // static loads (complete transitively before predecessor could trigger)
    float2 va2 = *(const float2*)(va + 2 * tid);
    float2 sA2 = *(const float2*)(g_sA + 2 * tid);
    float2 sW2 = *(const float2*)(g_sWe + 2 * tid);
    float2 bh2 = *(const float2*)(bhv + 2 * tid);
    int lane = tid & 31, wp = tid >> 5;

    pdl_wait();
    float2 hb = __half22float2(((const __half2*)(HB + (size_t)b * 512))[tid]);

    #pragma unroll
    for (int d = 0; d < 15; ++d) {
        int j = t - 15 + d;
        float m0, m1;
        if (j < 0) {
            m0 = sA2.x; m1 = sA2.y;
        } else {
            float2 f = fp8x2_to_f2(
                ((const __nv_fp8x2_storage_t*)(g_MEMA8 + (size_t)j * HSLOT + (size_t)b * 512))[tid]);
            m0 = f.x; m1 = f.y;
        }
        float s = va2.x * tanh_app(m0 + hb.x) + va2.y * tanh_app(m1 + hb.y);
        #pragma unroll
        for (int off = 16; off; off >>= 1) s += __shfl_xor_sync(0xffffffffu, s, off);
        if (lane == 0) sred[d][wp] = s;
    }
    __syncthreads();
    if (tid < 15) {
        float e = 0.f;
        #pragma unroll
        for (int w2 = 0; w2 < 8; ++w2) e += sred[tid][w2];
        se[tid] = e;
    }
    __syncthreads();

    float mx = -1e30f;
    #pragma unroll
    for (int d = 0; d < 15; ++d) mx = fmaxf(mx, se[d]);
    float al[15], sum = 0.f;
    #pragma unroll
    for (int d = 0; d < 15; ++d) { al[d] = __expf(se[d] - mx); sum += al[d]; }
    float inv = __fdividef(1.f, sum);
    float c0 = 0.f, c1 = 0.f;
    #pragma unroll
    for (int d = 0; d < 15; ++d) {
        int j = t - 15 + d;
        float a = al[d] * inv;
        float m0, m1;
        if (j < 0) {
            m0 = sW2.x; m1 = sW2.y;
        } else {
            float2 f = fp8x2_to_f2(
                ((const __nv_fp8x2_storage_t*)(g_HWE8 + (size_t)j * HSLOT + (size_t)b * 512))[tid]);
            m0 = f.x; m1 = f.y;
        }
        c0 = fmaf(a, m0, c0);
        c1 = fmaf(a, m1, c1);
    }
    float2 hg = __half22float2(((const __half2*)(HG + (size_t)b * 512))[tid]);
    float h0 = tanh_app(c0 + hg.x + bh2.x);
    float h1 = tanh_app(c1 + hg.y + bh2.y);
    pdl_trigger();
    ((__half2*)(AhNext + (size_t)b * 512))[tid] = __floats2half2_rn(h0, h1);
}

// ---------------- head layers 2,3 ----------------
__global__ void head2_k(const float* __restrict__ HD1, const float* __restrict__ W2,
                        const float* __restrict__ b2, float* __restrict__ HD2) {
    pdl_wait();
    int warp = (blockIdx.x * blockDim.x + threadIdx.x) >> 5;
    int lane = threadIdx.x & 31;
    if (warp >= Bn) { pdl_trigger(); return; }
    const float* h = HD1 + (size_t)warp * 256;
    float acc = 0.f;
    for (int k = 0; k < 256; ++k) acc = fmaf(h[k], W2[k * 32 + lane], acc);
    HD2[(size_t)warp * 32 + lane] = fmaxf(acc + b2[lane], 0.f);
    pdl_trigger();
}

__global__ void head3_k(const float* __restrict__ HD2, const float* __restrict__ W3,
                        const float* __restrict__ b3, float* __restrict__ out) {
    pdl_wait();
    int b = blockIdx.x * blockDim.x + threadIdx.x;
    if (b >= Bn) return;
    float a0 = b3[0], a1 = b3[1];
    const float* h = HD2 + (size_t)b * 32;
    #pragma unroll
    for (int k = 0; k < 32; ++k) {
        float hv = h[k];
        a0 = fmaf(hv, W3[k * 2 + 0], a0);
        a1 = fmaf(hv, W3[k * 2 + 1], a1);
    }
    float m = fmaxf(a0, a1);
    float e0v = expf(a0 - m), e1v = expf(a1 - m);
    float inv = 1.f / (e0v + e1v);
    out[(size_t)b * 2 + 0] = e0v * inv;
    out[(size_t)b * 2 + 1] = e1v * inv;
}

// ---------------- PDL launch helper ----------------
template <typename F, typename... Args>
static inline void launch_pdl(F f, dim3 grid, dim3 block, size_t smem, Args... args) {
    cudaLaunchConfig_t cfg = {};
    cfg.gridDim = grid;
    cfg.blockDim = block;
    cfg.dynamicSmemBytes = smem;
    cfg.stream = 0;
    cudaLaunchAttribute attr[1];
    attr[0].id = cudaLaunchAttributeProgrammaticStreamSerialization;
    attr[0].val.programmaticStreamSerializationAllowed = 1;
    cfg.attrs = attr;
    cfg.numAttrs = 1;
    cudaLaunchKernelEx(&cfg, f, args...);
}

// ---------------- launcher ----------------
extern "C" void kernel_launch(void* const* d_in, const int* in_sizes, int n_in,
                              void* d_out, int out_size) {
    const float* inputs    = (const float*)d_in[0];
    const float* init_proj = (const float*)d_in[1];
    const float* Wx  = (const float*)d_in[3];
    const float* Uh  = (const float*)d_in[4];
    const float* Wt  = (const float*)d_in[5];
    const float* b   = (const float*)d_in[6];
    const float* WxT = (const float*)d_in[7];
    const float* WtT = (const float*)d_in[8];
    const float* bT  = (const float*)d_in[9];
    const float* Wa  = (const float*)d_in[10];
    const float* Wb  = (const float*)d_in[11];
    const float* va  = (const float*)d_in[12];
    const float* ba  = (const float*)d_in[13];
    const float* We  = (const float*)d_in[14];
    const float* Wg  = (const float*)d_in[15];
    const float* bh  = (const float*)d_in[16];
    const float* W1  = (const float*)d_in[17];
    const float* b1  = (const float*)d_in[18];
    const float* W2  = (const float*)d_in[19];
    const float* b2  = (const float*)d_in[20];
    const float* W3  = (const float*)d_in[21];
    const float* b3  = (const float*)d_in[22];
    float* out = (float*)d_out;

    cudaFuncSetAttribute(mma_gemm<1>, cudaFuncAttributeMaxDynamicSharedMemorySize, SMEM_BYTES);
    cudaFuncSetAttribute(mma_gemm<2>, cudaFuncAttributeMaxDynamicSharedMemorySize, SMEM_BYTES);
    cudaFuncSetAttribute(mma_gemm<4>, cudaFuncAttributeMaxDynamicSharedMemorySize, SMEM_BYTES);
    cudaFuncSetAttribute(mma_gemm<5>, cudaFuncAttributeMaxDynamicSharedMemorySize, SMEM_BYTES);

    __half *Ah, *APRE, *WTb, *WPRE, *WT2, *WTh, *ZX16, *TG16, *HcH, *HBh, *HGh;
    unsigned char *MEMA8, *HWE8;
    float *C, *HD1, *HD2;
    cudaGetSymbolAddress((void**)&Ah, g_Ah);
    cudaGetSymbolAddress((void**)&APRE, g_APRE);
    cudaGetSymbolAddress((void**)&WTb, g_WTb);
    cudaGetSymbolAddress((void**)&WPRE, g_WPRE);
    cudaGetSymbolAddress((void**)&WT2, g_WT2);
    cudaGetSymbolAddress((void**)&WTh, g_WTh);
    cudaGetSymbolAddress((void**)&MEMA8, g_MEMA8);
    cudaGetSymbolAddress((void**)&HWE8, g_HWE8);
    cudaGetSymbolAddress((void**)&ZX16, g_ZX16);
    cudaGetSymbolAddress((void**)&TG16, g_TG16);
    cudaGetSymbolAddress((void**)&HcH, g_HcH);
    cudaGetSymbolAddress((void**)&HBh, g_HBh);
    cudaGetSymbolAddress((void**)&HGh, g_HGh);
    cudaGetSymbolAddress((void**)&C, g_C);
    cudaGetSymbolAddress((void**)&HD1, g_HD1);
    cudaGetSymbolAddress((void**)&HD2, g_HD2);

    prep_weights<<<1024, 256>>>(Uh, Wx, Wt, Wa, WxT, Wb, Wg, We, W1);
    prep_s<<<1, 512>>>(init_proj);
    prep_sA<<<1, 512>>>(Wa, We);
    prep_A<<<2048, 256>>>(inputs);

    // pre-GEMM: ZX(perm) + TG for all steps
    mma_gemm<5><<<dim3(20, 512), 256, SMEM_BYTES>>>(
        APRE, 64, 64, WPRE,
        b, (float*)nullptr,
        (unsigned char*)nullptr, (unsigned char*)nullptr, (__half*)nullptr, (__half*)nullptr,
        (const __half*)nullptr, (const __half*)nullptr, (float*)nullptr,
        inputs, WtT, bT);

    for (int t = 0; t < 16; ++t) {
        if (t > 0) {
            launch_pdl(mma_gemm<1>, dim3(24, 32), dim3(256), (size_t)SMEM_BYTES,
                (const __half*)(Ah + (size_t)t * HSLOT), 512, 512,
                (const __half*)WTb,
                (const float*)nullptr, (float*)nullptr,
                (unsigned char*)(MEMA8 + (size_t)(t - 1) * HSLOT),
                (unsigned char*)(HWE8 + (size_t)(t - 1) * HSLOT),
                (__half*)nullptr, (__half*)HcH,
                (const __half*)(ZX16 + (size_t)t * Bn * 2048),
                (const __half*)(TG16 + (size_t)t * Bn * 512),
                (float*)C,
                (const float*)nullptr, (const float*)nullptr, (const float*)nullptr);
        } else {
            launch_pdl(gates0_k, dim3(8192), dim3(256), (size_t)0,
                (const __half*)ZX16, (const __half*)TG16, (float*)C, (__half*)HcH);
        }
        launch_pdl(mma_gemm<2>, dim3(8, 32), dim3(256), (size_t)SMEM_BYTES,
            (const __half*)HcH, 512, 512,
            (const __half*)WT2,
            (const float*)ba, (float*)nullptr,
            (unsigned char*)nullptr, (unsigned char*)nullptr,
            (__half*)HBh, (__half*)HGh,
            (const __half*)nullptr, (const __half*)nullptr, (float*)nullptr,
            (const float*)nullptr, (const float*)nullptr, (const float*)nullptr);
        launch_pdl(attn_k, dim3(4096), dim3(256), (size_t)0,
            (const __half*)HBh, (const __half*)HGh,
            (const float*)va, (const float*)bh,
            (__half*)(Ah + (size_t)(t + 1) * HSLOT), t);
    }

    launch_pdl(mma_gemm<4>, dim3(2, 32), dim3(256), (size_t)SMEM_BYTES,
        (const __half*)(Ah + (size_t)16 * HSLOT), 512, 512,
        (const __half*)WTh,
        (const float*)b1, (float*)HD1,
        (unsigned char*)nullptr, (unsigned char*)nullptr, (__half*)nullptr, (__half*)nullptr,
        (const __half*)nullptr, (const __half*)nullptr, (float*)nullptr,
        (const float*)nullptr, (const float*)nullptr, (const float*)nullptr);
    launch_pdl(head2_k, dim3(512), dim3(256), (size_t)0,
        (const float*)HD1, (const float*)W2, (const float*)b2, (float*)HD2);
    launch_pdl(head3_k, dim3(16), dim3(256), (size_t)0,
        (const float*)HD2, (const float*)W3, (const float*)b3, (float*)out);
}